// round 6
// baseline (speedup 1.0000x reference)
#include <cuda_runtime.h>
#include <cuda_fp16.h>
#include <math.h>

// ---------------- problem constants ----------------
#define B   32
#define H0  480
#define W0  640
#define H1  240
#define W1  320
#define H2  120
#define W2  160
#define H3  60
#define W3  80
#define N3  (H3*W3)   // 4800

// ---------------- scratch (device globals; no runtime alloc) ----------------
__device__ __half g_f1[B * 32 * H1 * W1];   // 157 MB
__device__ __half g_f2[B * 64 * H2 * W2];   //  78 MB
__device__ float  g_f3[B * 64 * H3 * W3];   //  39 MB
__device__ float  g_logits[B * N3];
__device__ float  g_wts[B * N3];
__device__ float  g_pooled[B * 64];

// ---------------- packed f32x2 helpers (Blackwell FFMA2) ----------------
typedef unsigned long long u64;

__device__ __forceinline__ u64 pack2(float x, float y) {
    u64 r; asm("mov.b64 %0, {%1, %2};" : "=l"(r) : "f"(x), "f"(y)); return r;
}
__device__ __forceinline__ void unpack2(u64 v, float& x, float& y) {
    asm("mov.b64 {%0, %1}, %2;" : "=f"(x), "=f"(y) : "l"(v));
}
__device__ __forceinline__ u64 dup2(float x) { return pack2(x, x); }
__device__ __forceinline__ u64 ffma2(u64 a, u64 b, u64 c) {
    u64 d; asm("fma.rn.f32x2 %0, %1, %2, %3;" : "=l"(d) : "l"(a), "l"(b), "l"(c));
    return d;
}

__device__ __forceinline__ float elu(float x) {
    return x > 0.0f ? x : (__expf(x) - 1.0f);
}

// ================= kernel 1: coords + dw1 + pw1 + ELU, 2 pixels/thread =================
__global__ void k1_dwsep1(const float* __restrict__ flow,
                          const float* __restrict__ dw1,     // (5,1,3,3)
                          const float* __restrict__ pw1_w,   // (32,5)
                          const float* __restrict__ pw1_b)   // (32,)
{
    __shared__ u64 s_dw[5 * 9];
    __shared__ u64 s_pw[32 * 5];
    __shared__ u64 s_pb[32];
    for (int i = threadIdx.x; i < 45;  i += blockDim.x) s_dw[i] = dup2(dw1[i]);
    for (int i = threadIdx.x; i < 160; i += blockDim.x) s_pw[i] = dup2(pw1_w[i]);
    for (int i = threadIdx.x; i < 32;  i += blockDim.x) s_pb[i] = dup2(pw1_b[i]);
    __syncthreads();

    const int WP = W1 / 2;
    int idx = blockIdx.x * blockDim.x + threadIdx.x;
    if (idx >= B * H1 * WP) return;
    int tx = idx % WP;
    int t  = idx / WP;
    int oy = t % H1;
    int b  = t / H1;

    const float sx = 2.0f / (float)(W0 - 1);
    const float sy = 2.0f / (float)(H0 - 1);

    int col0 = 4 * tx - 2;
    bool left_ok = (tx > 0);

    float fxm1 = -1.0f + sx * (float)(4 * tx - 1);
    float fx0  = -1.0f + sx * (float)(4 * tx + 0);
    float fx1  = -1.0f + sx * (float)(4 * tx + 1);
    float fx2  = -1.0f + sx * (float)(4 * tx + 2);
    float fx3  = -1.0f + sx * (float)(4 * tx + 3);

    u64 dwv[5];
    #pragma unroll
    for (int c = 0; c < 5; c++) dwv[c] = pack2(0.f, 0.f);

    const float* f0 = flow + ((size_t)b * 2 + 0) * (H0 * W0);
    const float* f1p = flow + ((size_t)b * 2 + 1) * (H0 * W0);

    #pragma unroll
    for (int ky = 0; ky < 3; ky++) {
        int iy = oy * 2 - 1 + ky;
        if ((unsigned)iy >= H0) continue;
        float fy = -1.0f + sy * (float)iy;
        float fy2 = fy * fy;

        const float* r0 = f0 + (size_t)iy * W0 + col0;
        const float* r1 = f1p + (size_t)iy * W0 + col0;
        float2 A0 = left_ok ? *(const float2*)(r0)     : make_float2(0.f, 0.f);
        float2 B0 = *(const float2*)(r0 + 2);
        float2 C0 = *(const float2*)(r0 + 4);
        float2 A1 = left_ok ? *(const float2*)(r1)     : make_float2(0.f, 0.f);
        float2 B1 = *(const float2*)(r1 + 2);
        float2 C1 = *(const float2*)(r1 + 4);

        u64 t0c0 = pack2(A0.y, B0.y), t1c0 = pack2(B0.x, C0.x), t2c0 = pack2(B0.y, C0.y);
        u64 t0c1 = pack2(A1.y, B1.y), t1c1 = pack2(B1.x, C1.x), t2c1 = pack2(B1.y, C1.y);

        u64 t0c2 = pack2(left_ok ? fxm1 : 0.f, fx1);
        u64 t1c2 = pack2(fx0, fx2);
        u64 t2c2 = pack2(fx1, fx3);

        u64 t0c3 = pack2(left_ok ? fy : 0.f, fy);
        u64 t1c3 = dup2(fy);
        u64 t2c3 = dup2(fy);

        u64 t0c4 = pack2(left_ok ? (fxm1 * fxm1 + fy2) : 0.f, fx1 * fx1 + fy2);
        u64 t1c4 = pack2(fx0 * fx0 + fy2, fx2 * fx2 + fy2);
        u64 t2c4 = pack2(fx1 * fx1 + fy2, fx3 * fx3 + fy2);

        int wb = ky * 3;
        dwv[0] = ffma2(s_dw[0 * 9 + wb + 0], t0c0, dwv[0]);
        dwv[0] = ffma2(s_dw[0 * 9 + wb + 1], t1c0, dwv[0]);
        dwv[0] = ffma2(s_dw[0 * 9 + wb + 2], t2c0, dwv[0]);
        dwv[1] = ffma2(s_dw[1 * 9 + wb + 0], t0c1, dwv[1]);
        dwv[1] = ffma2(s_dw[1 * 9 + wb + 1], t1c1, dwv[1]);
        dwv[1] = ffma2(s_dw[1 * 9 + wb + 2], t2c1, dwv[1]);
        dwv[2] = ffma2(s_dw[2 * 9 + wb + 0], t0c2, dwv[2]);
        dwv[2] = ffma2(s_dw[2 * 9 + wb + 1], t1c2, dwv[2]);
        dwv[2] = ffma2(s_dw[2 * 9 + wb + 2], t2c2, dwv[2]);
        dwv[3] = ffma2(s_dw[3 * 9 + wb + 0], t0c3, dwv[3]);
        dwv[3] = ffma2(s_dw[3 * 9 + wb + 1], t1c3, dwv[3]);
        dwv[3] = ffma2(s_dw[3 * 9 + wb + 2], t2c3, dwv[3]);
        dwv[4] = ffma2(s_dw[4 * 9 + wb + 0], t0c4, dwv[4]);
        dwv[4] = ffma2(s_dw[4 * 9 + wb + 1], t1c4, dwv[4]);
        dwv[4] = ffma2(s_dw[4 * 9 + wb + 2], t2c4, dwv[4]);
    }

    __half2* outp = (__half2*)(g_f1 + ((size_t)b * 32) * (H1 * W1) + (size_t)oy * W1) + tx;
    #pragma unroll
    for (int o = 0; o < 32; o++) {
        u64 acc = s_pb[o];
        #pragma unroll
        for (int c = 0; c < 5; c++) acc = ffma2(s_pw[o * 5 + c], dwv[c], acc);
        float v0, v1; unpack2(acc, v0, v1);
        outp[(size_t)o * (H1 * W1 / 2)] = __floats2half2_rn(elu(v0), elu(v1));
    }
}

// ================= kernel 2 (TILED): dwsep 32->64, out tile 16x4 =================
// phase0: load input tile (32ch x 9rows x 33cols) into smem
// phase1: depthwise -> s_dwv[32][64] (fp32)
// phase2: pointwise FFMA2 (pixel pairs), 8 out-channels per thread
__global__ __launch_bounds__(256) void k2_tiled(const __half* __restrict__ in,
                         const float* __restrict__ dw,    // (32,1,3,3)
                         const float* __restrict__ pw_w,  // (64,32)
                         const float* __restrict__ pw_b,  // (64,)
                         __half* __restrict__ out)
{
    __shared__ __half s_in[32][9][34];                 // 19584 B
    __shared__ float  s_dw[32 * 9];                    //  1152 B
    __shared__ __align__(16) float s_dwv[32][64];      //  8192 B
    __shared__ u64    s_pwd[64][32];                   // 16384 B
    __shared__ u64    s_pbd[64];                       //   512 B

    int tid = threadIdx.x;
    int tile = blockIdx.x;                 // 10 x 30 x B
    int txi = tile % 10;  int tmp = tile / 10;
    int tyi = tmp % 30;   int b   = tmp / 30;
    int ox0 = txi * 16, oy0 = tyi * 4;

    for (int i = tid; i < 288; i += 256) s_dw[i] = dw[i];
    for (int i = tid; i < 64 * 32; i += 256) {
        int o = i >> 5, c = i & 31;
        s_pwd[o][c] = dup2(pw_w[i]);
    }
    if (tid < 64) s_pbd[tid] = dup2(pw_b[tid]);

    // phase0: input tile
    {
        const __half* base = in + (size_t)b * 32 * (H1 * W1);
        int iy0 = 2 * oy0 - 1, ix0 = 2 * ox0 - 1;
        for (int i = tid; i < 32 * 9 * 34; i += 256) {
            int c = i / 306;
            int r = (i / 34) % 9;
            int col = i % 34;
            int iy = iy0 + r, ix = ix0 + col;
            __half v = __float2half(0.f);
            if (col < 33 && (unsigned)iy < H1 && (unsigned)ix < W1)
                v = base[(size_t)c * (H1 * W1) + (size_t)iy * W1 + ix];
            s_in[c][r][col] = v;
        }
    }
    __syncthreads();

    // phase1: depthwise
    {
        int px = tid & 63;
        int tx = px & 15, ty = px >> 4;
        #pragma unroll
        for (int i = 0; i < 8; i++) {
            int c = (tid >> 6) + 4 * i;
            float acc = 0.f;
            #pragma unroll
            for (int ky = 0; ky < 3; ky++)
                #pragma unroll
                for (int kx = 0; kx < 3; kx++)
                    acc = fmaf(s_dw[c * 9 + ky * 3 + kx],
                               __half2float(s_in[c][2 * ty + ky][2 * tx + kx]), acc);
            s_dwv[c][px] = acc;
        }
    }
    __syncthreads();

    // phase2: pointwise (pixel-pair FFMA2)
    {
        int p2  = tid & 31;            // pixel pair 0..31
        int ocb = (tid >> 5) * 8;      // 8 out channels
        u64 acc[8];
        #pragma unroll
        for (int j = 0; j < 8; j++) acc[j] = s_pbd[ocb + j];
        #pragma unroll 8
        for (int c = 0; c < 32; c++) {
            u64 dwp = *(const u64*)&s_dwv[c][2 * p2];
            #pragma unroll
            for (int j = 0; j < 8; j++)
                acc[j] = ffma2(s_pwd[ocb + j][c], dwp, acc[j]);
        }
        int row = p2 >> 3, colp = p2 & 7;
        int oy = oy0 + row, ox = ox0 + 2 * colp;
        __half2* op = (__half2*)(out + (size_t)b * 64 * (H2 * W2) + (size_t)oy * W2 + ox);
        #pragma unroll
        for (int j = 0; j < 8; j++) {
            float v0, v1; unpack2(acc[j], v0, v1);
            op[(size_t)(ocb + j) * (H2 * W2 / 2)] = __floats2half2_rn(elu(v0), elu(v1));
        }
    }
}

// ================= kernel 3 (TILED): dwsep 64->64 + attn logit, out tile 8x4 =================
// phase2 packs OUT-CHANNEL pairs (oc-pair FFMA2); logit accumulated via smem atomics.
__global__ __launch_bounds__(256) void k3_tiled(const __half* __restrict__ in,
                         const float* __restrict__ dw,     // (64,1,3,3)
                         const float* __restrict__ pw_w,   // (64,64)
                         const float* __restrict__ pw_b,   // (64,)
                         const float* __restrict__ attn_w, // (64,)
                         const float* __restrict__ attn_b, // (1,)
                         float* __restrict__ f3,
                         float* __restrict__ logits)
{
    __shared__ __half s_in[64][9][18];                 // 20736 B
    __shared__ float  s_dw[64 * 9];                    //  2304 B
    __shared__ __align__(16) float s_dwv[64][32];      //  8192 B
    __shared__ u64    s_pw2[32][64];                   // 16384 B (oc-pair packed)
    __shared__ u64    s_pb2[32];                       //   256 B
    __shared__ u64    s_aw2[32];                       //   256 B
    __shared__ float  s_logit[32];                     //   128 B

    int tid = threadIdx.x;
    int tile = blockIdx.x;                 // 10 x 15 x B
    int txi = tile % 10;  int tmp = tile / 10;
    int tyi = tmp % 15;   int b   = tmp / 15;
    int ox0 = txi * 8, oy0 = tyi * 4;

    for (int i = tid; i < 576; i += 256) s_dw[i] = dw[i];
    for (int i = tid; i < 32 * 64; i += 256) {
        int o2 = i >> 6, c = i & 63;
        s_pw2[o2][c] = pack2(pw_w[(2 * o2) * 64 + c], pw_w[(2 * o2 + 1) * 64 + c]);
    }
    if (tid < 32) {
        s_pb2[tid] = pack2(pw_b[2 * tid], pw_b[2 * tid + 1]);
        s_aw2[tid] = pack2(attn_w[2 * tid], attn_w[2 * tid + 1]);
        s_logit[tid] = 0.f;
    }

    // phase0: input tile (64ch x 9rows x 17cols)
    {
        const __half* base = in + (size_t)b * 64 * (H2 * W2);
        int iy0 = 2 * oy0 - 1, ix0 = 2 * ox0 - 1;
        for (int i = tid; i < 64 * 9 * 18; i += 256) {
            int c = i / 162;
            int r = (i / 18) % 9;
            int col = i % 18;
            int iy = iy0 + r, ix = ix0 + col;
            __half v = __float2half(0.f);
            if (col < 17 && (unsigned)iy < H2 && (unsigned)ix < W2)
                v = base[(size_t)c * (H2 * W2) + (size_t)iy * W2 + ix];
            s_in[c][r][col] = v;
        }
    }
    __syncthreads();

    // phase1: depthwise 32px x 64c
    {
        int px = tid & 31;
        int tx = px & 7, ty = px >> 3;
        #pragma unroll
        for (int i = 0; i < 8; i++) {
            int c = (tid >> 5) + 8 * i;
            float acc = 0.f;
            #pragma unroll
            for (int ky = 0; ky < 3; ky++)
                #pragma unroll
                for (int kx = 0; kx < 3; kx++)
                    acc = fmaf(s_dw[c * 9 + ky * 3 + kx],
                               __half2float(s_in[c][2 * ty + ky][2 * tx + kx]), acc);
            s_dwv[c][px] = acc;
        }
    }
    __syncthreads();

    // phase2: pointwise oc-pair FFMA2 + ELU + logit
    {
        int px = tid & 31;
        int tx = px & 7, ty = px >> 3;
        int oy = oy0 + ty, ox = ox0 + tx;
        int gpix = oy * W3 + ox;

        u64 acc[4];
        int ocp[4];
        #pragma unroll
        for (int j = 0; j < 4; j++) {
            ocp[j] = (tid >> 5) + 8 * j;
            acc[j] = s_pb2[ocp[j]];
        }
        #pragma unroll 8
        for (int c = 0; c < 64; c++) {
            u64 dwdup = dup2(s_dwv[c][px]);
            #pragma unroll
            for (int j = 0; j < 4; j++)
                acc[j] = ffma2(s_pw2[ocp[j]][c], dwdup, acc[j]);
        }

        float* f3b = f3 + (size_t)b * 64 * N3 + gpix;
        float lp = 0.f;
        #pragma unroll
        for (int j = 0; j < 4; j++) {
            float v0, v1; unpack2(acc[j], v0, v1);
            v0 = elu(v0); v1 = elu(v1);
            f3b[(size_t)(2 * ocp[j])     * N3] = v0;
            f3b[(size_t)(2 * ocp[j] + 1) * N3] = v1;
            float a0, a1; unpack2(s_aw2[ocp[j]], a0, a1);
            lp = fmaf(a0, v0, lp);
            lp = fmaf(a1, v1, lp);
        }
        atomicAdd(&s_logit[px], lp);
    }
    __syncthreads();

    if (tid < 32) {
        int ty = tid >> 3, tx = tid & 7;
        logits[(size_t)b * N3 + (size_t)(oy0 + ty) * W3 + (ox0 + tx)] =
            s_logit[tid] + attn_b[0];
    }
}

// ================= kernel 4a: per-batch softmax -> normalized weights =================
#define SMX_T 512
__global__ void k4a_softmax()
{
    __shared__ float s_l[N3];
    __shared__ float s_red[SMX_T / 32];
    __shared__ float s_bcast;

    int b = blockIdx.x;
    int tid = threadIdx.x;
    int lane = tid & 31, warp = tid >> 5;
    const float* lg = g_logits + (size_t)b * N3;
    float* wt = g_wts + (size_t)b * N3;

    float lmax = -1e30f;
    for (int n = tid; n < N3; n += SMX_T) {
        float v = lg[n];
        s_l[n] = v;
        lmax = fmaxf(lmax, v);
    }
    #pragma unroll
    for (int o = 16; o > 0; o >>= 1) lmax = fmaxf(lmax, __shfl_xor_sync(0xffffffff, lmax, o));
    if (lane == 0) s_red[warp] = lmax;
    __syncthreads();
    if (warp == 0) {
        float v = (lane < SMX_T / 32) ? s_red[lane] : -1e30f;
        #pragma unroll
        for (int o = 16; o > 0; o >>= 1) v = fmaxf(v, __shfl_xor_sync(0xffffffff, v, o));
        if (lane == 0) s_bcast = v;
    }
    __syncthreads();
    float gmax = s_bcast;

    float lsum = 0.f;
    for (int n = tid; n < N3; n += SMX_T) {
        float e = expf(s_l[n] - gmax);
        s_l[n] = e;
        lsum += e;
    }
    #pragma unroll
    for (int o = 16; o > 0; o >>= 1) lsum += __shfl_xor_sync(0xffffffff, lsum, o);
    if (lane == 0) s_red[warp] = lsum;
    __syncthreads();
    if (warp == 0) {
        float v = (lane < SMX_T / 32) ? s_red[lane] : 0.f;
        #pragma unroll
        for (int o = 16; o > 0; o >>= 1) v += __shfl_xor_sync(0xffffffff, v, o);
        if (lane == 0) s_bcast = v;
    }
    __syncthreads();
    float inv_sum = 1.0f / s_bcast;

    for (int n = tid; n < N3; n += SMX_T) wt[n] = s_l[n] * inv_sum;
}

// ================= kernel 4b: pooled[b][c] = dot(f3[b,c,:], wts[b,:]) =================
#define POOL_T 256
__global__ void k4b_pool()
{
    int c = blockIdx.x;
    int b = blockIdx.y;
    int tid = threadIdx.x;
    int lane = tid & 31, warp = tid >> 5;
    __shared__ float s_red[POOL_T / 32];

    const float* fc = g_f3 + ((size_t)b * 64 + c) * N3;
    const float* wt = g_wts + (size_t)b * N3;

    float acc = 0.f;
    for (int n = tid; n < N3; n += POOL_T)
        acc = fmaf(wt[n], fc[n], acc);
    #pragma unroll
    for (int o = 16; o > 0; o >>= 1) acc += __shfl_xor_sync(0xffffffff, acc, o);
    if (lane == 0) s_red[warp] = acc;
    __syncthreads();
    if (warp == 0) {
        float v = (lane < POOL_T / 32) ? s_red[lane] : 0.f;
        #pragma unroll
        for (int o = 16; o > 0; o >>= 1) v += __shfl_xor_sync(0xffffffff, v, o);
        if (lane == 0) g_pooled[b * 64 + c] = v;
    }
}

// ================= kernel 5: MLP + GRU + fc (1 block / batch) =================
__global__ void k5_head(const float* __restrict__ mlp1_w, const float* __restrict__ mlp1_b,
                        const float* __restrict__ mlp2_w, const float* __restrict__ mlp2_b,
                        const float* __restrict__ w_ih,   const float* __restrict__ b_ih,
                        const float* __restrict__ b_hh,
                        const float* __restrict__ fc_w,   const float* __restrict__ fc_b,
                        float* __restrict__ out)
{
    __shared__ float s_pool[64];
    __shared__ float s_h1[32];
    __shared__ float s_om[3];
    __shared__ float s_gi[96];
    __shared__ float s_h[32];

    int b = blockIdx.x;
    int t = threadIdx.x;

    if (t < 64) s_pool[t] = g_pooled[b * 64 + t];
    __syncthreads();

    if (t < 32) {
        float acc = mlp1_b[t];
        #pragma unroll
        for (int c = 0; c < 64; c++) acc = fmaf(mlp1_w[t * 64 + c], s_pool[c], acc);
        s_h1[t] = acc > 0.f ? acc : (expf(acc) - 1.f);
    }
    __syncthreads();

    if (t < 3) {
        float acc = mlp2_b[t];
        #pragma unroll
        for (int c = 0; c < 32; c++) acc = fmaf(mlp2_w[t * 32 + c], s_h1[c], acc);
        s_om[t] = acc;
    }
    __syncthreads();

    if (t < 96) {
        float acc = b_ih[t];
        #pragma unroll
        for (int k = 0; k < 3; k++) acc = fmaf(w_ih[t * 3 + k], s_om[k], acc);
        s_gi[t] = acc;
    }
    __syncthreads();

    if (t < 32) {
        float r = 1.0f / (1.0f + expf(-(s_gi[t]      + b_hh[t])));
        float z = 1.0f / (1.0f + expf(-(s_gi[32 + t] + b_hh[32 + t])));
        float n = tanhf(s_gi[64 + t] + r * b_hh[64 + t]);
        s_h[t] = (1.0f - z) * n;
    }
    __syncthreads();

    if (t < 3) {
        float d = fc_b[t];
        #pragma unroll
        for (int j = 0; j < 32; j++) d = fmaf(fc_w[t * 32 + j], s_h[j], d);
        out[b * 3 + t] = s_om[t] + d;
    }
}

// ================= launch =================
extern "C" void kernel_launch(void* const* d_in, const int* in_sizes, int n_in,
                              void* d_out, int out_size)
{
    const float* flow   = (const float*)d_in[0];
    const float* dw1    = (const float*)d_in[1];
    const float* pw1_w  = (const float*)d_in[2];
    const float* pw1_b  = (const float*)d_in[3];
    const float* dw2    = (const float*)d_in[4];
    const float* pw2_w  = (const float*)d_in[5];
    const float* pw2_b  = (const float*)d_in[6];
    const float* dw3    = (const float*)d_in[7];
    const float* pw3_w  = (const float*)d_in[8];
    const float* pw3_b  = (const float*)d_in[9];
    const float* attn_w = (const float*)d_in[10];
    const float* attn_b = (const float*)d_in[11];
    const float* mlp1_w = (const float*)d_in[12];
    const float* mlp1_b = (const float*)d_in[13];
    const float* mlp2_w = (const float*)d_in[14];
    const float* mlp2_b = (const float*)d_in[15];
    const float* w_ih   = (const float*)d_in[16];
    // d_in[17] = w_hh (unused: h0 == 0)
    const float* b_ih   = (const float*)d_in[18];
    const float* b_hh   = (const float*)d_in[19];
    const float* fc_w   = (const float*)d_in[20];
    const float* fc_b   = (const float*)d_in[21];
    float* out = (float*)d_out;

    __half* f1; cudaGetSymbolAddress((void**)&f1, g_f1);
    __half* f2; cudaGetSymbolAddress((void**)&f2, g_f2);
    float*  f3; cudaGetSymbolAddress((void**)&f3, g_f3);
    float*  lg; cudaGetSymbolAddress((void**)&lg, g_logits);

    {
        int total = B * H1 * (W1 / 2);
        k1_dwsep1<<<(total + 255) / 256, 256>>>(flow, dw1, pw1_w, pw1_b);
    }
    // k2: out tile 16x4 -> (160/16)x(120/4) = 10x30 tiles per batch
    k2_tiled<<<10 * 30 * B, 256>>>(f1, dw2, pw2_w, pw2_b, f2);
    // k3: out tile 8x4 -> (80/8)x(60/4) = 10x15 tiles per batch
    k3_tiled<<<10 * 15 * B, 256>>>(f2, dw3, pw3_w, pw3_b, attn_w, attn_b, f3, lg);
    k4a_softmax<<<B, SMX_T>>>();
    {
        dim3 grid(64, B);
        k4b_pool<<<grid, POOL_T>>>();
    }
    k5_head<<<B, 96>>>(mlp1_w, mlp1_b, mlp2_w, mlp2_b,
                       w_ih, b_ih, b_hh, fc_w, fc_b, out);
}

// round 7
// speedup vs baseline: 1.6950x; 1.6950x over previous
#include <cuda_runtime.h>
#include <cuda_fp16.h>
#include <math.h>

// ---------------- problem constants ----------------
#define B   32
#define H0  480
#define W0  640
#define H1  240
#define W1  320
#define H2  120
#define W2  160
#define H3  60
#define W3  80
#define N3  (H3*W3)   // 4800

// ---------------- scratch (device globals; no runtime alloc) ----------------
__device__ __half g_f1[B * 32 * H1 * W1];   // 157 MB
__device__ __half g_f2[B * 64 * H2 * W2];   //  78 MB
__device__ float  g_f3[B * 64 * H3 * W3];   //  39 MB
__device__ float  g_logits[B * N3];
__device__ float  g_wts[B * N3];
__device__ float  g_pooled[B * 64];

// ---------------- packed f32x2 helpers (Blackwell FFMA2) ----------------
typedef unsigned long long u64;

__device__ __forceinline__ u64 pack2(float x, float y) {
    u64 r; asm("mov.b64 %0, {%1, %2};" : "=l"(r) : "f"(x), "f"(y)); return r;
}
__device__ __forceinline__ void unpack2(u64 v, float& x, float& y) {
    asm("mov.b64 {%0, %1}, %2;" : "=f"(x), "=f"(y) : "l"(v));
}
__device__ __forceinline__ u64 dup2(float x) { return pack2(x, x); }
__device__ __forceinline__ u64 ffma2(u64 a, u64 b, u64 c) {
    u64 d; asm("fma.rn.f32x2 %0, %1, %2, %3;" : "=l"(d) : "l"(a), "l"(b), "l"(c));
    return d;
}

__device__ __forceinline__ float elu(float x) {
    return x > 0.0f ? x : (__expf(x) - 1.0f);
}

// ================= kernel 1: coords + dw1 + pw1 + ELU, 2 pixels/thread =================
__global__ void k1_dwsep1(const float* __restrict__ flow,
                          const float* __restrict__ dw1,     // (5,1,3,3)
                          const float* __restrict__ pw1_w,   // (32,5)
                          const float* __restrict__ pw1_b)   // (32,)
{
    __shared__ u64 s_dw[5 * 9];
    __shared__ u64 s_pw[32 * 5];
    __shared__ u64 s_pb[32];
    for (int i = threadIdx.x; i < 45;  i += blockDim.x) s_dw[i] = dup2(dw1[i]);
    for (int i = threadIdx.x; i < 160; i += blockDim.x) s_pw[i] = dup2(pw1_w[i]);
    for (int i = threadIdx.x; i < 32;  i += blockDim.x) s_pb[i] = dup2(pw1_b[i]);
    __syncthreads();

    const int WP = W1 / 2;
    int idx = blockIdx.x * blockDim.x + threadIdx.x;
    if (idx >= B * H1 * WP) return;
    int tx = idx % WP;
    int t  = idx / WP;
    int oy = t % H1;
    int b  = t / H1;

    const float sx = 2.0f / (float)(W0 - 1);
    const float sy = 2.0f / (float)(H0 - 1);

    int col0 = 4 * tx - 2;
    bool left_ok = (tx > 0);

    float fxm1 = -1.0f + sx * (float)(4 * tx - 1);
    float fx0  = -1.0f + sx * (float)(4 * tx + 0);
    float fx1  = -1.0f + sx * (float)(4 * tx + 1);
    float fx2  = -1.0f + sx * (float)(4 * tx + 2);
    float fx3  = -1.0f + sx * (float)(4 * tx + 3);

    u64 dwv[5];
    #pragma unroll
    for (int c = 0; c < 5; c++) dwv[c] = pack2(0.f, 0.f);

    const float* f0 = flow + ((size_t)b * 2 + 0) * (H0 * W0);
    const float* f1p = flow + ((size_t)b * 2 + 1) * (H0 * W0);

    #pragma unroll
    for (int ky = 0; ky < 3; ky++) {
        int iy = oy * 2 - 1 + ky;
        if ((unsigned)iy >= H0) continue;
        float fy = -1.0f + sy * (float)iy;
        float fy2 = fy * fy;

        const float* r0 = f0 + (size_t)iy * W0 + col0;
        const float* r1 = f1p + (size_t)iy * W0 + col0;
        float2 A0 = left_ok ? *(const float2*)(r0)     : make_float2(0.f, 0.f);
        float2 B0 = *(const float2*)(r0 + 2);
        float2 C0 = *(const float2*)(r0 + 4);
        float2 A1 = left_ok ? *(const float2*)(r1)     : make_float2(0.f, 0.f);
        float2 B1 = *(const float2*)(r1 + 2);
        float2 C1 = *(const float2*)(r1 + 4);

        u64 t0c0 = pack2(A0.y, B0.y), t1c0 = pack2(B0.x, C0.x), t2c0 = pack2(B0.y, C0.y);
        u64 t0c1 = pack2(A1.y, B1.y), t1c1 = pack2(B1.x, C1.x), t2c1 = pack2(B1.y, C1.y);

        u64 t0c2 = pack2(left_ok ? fxm1 : 0.f, fx1);
        u64 t1c2 = pack2(fx0, fx2);
        u64 t2c2 = pack2(fx1, fx3);

        u64 t0c3 = pack2(left_ok ? fy : 0.f, fy);
        u64 t1c3 = dup2(fy);
        u64 t2c3 = dup2(fy);

        u64 t0c4 = pack2(left_ok ? (fxm1 * fxm1 + fy2) : 0.f, fx1 * fx1 + fy2);
        u64 t1c4 = pack2(fx0 * fx0 + fy2, fx2 * fx2 + fy2);
        u64 t2c4 = pack2(fx1 * fx1 + fy2, fx3 * fx3 + fy2);

        int wb = ky * 3;
        dwv[0] = ffma2(s_dw[0 * 9 + wb + 0], t0c0, dwv[0]);
        dwv[0] = ffma2(s_dw[0 * 9 + wb + 1], t1c0, dwv[0]);
        dwv[0] = ffma2(s_dw[0 * 9 + wb + 2], t2c0, dwv[0]);
        dwv[1] = ffma2(s_dw[1 * 9 + wb + 0], t0c1, dwv[1]);
        dwv[1] = ffma2(s_dw[1 * 9 + wb + 1], t1c1, dwv[1]);
        dwv[1] = ffma2(s_dw[1 * 9 + wb + 2], t2c1, dwv[1]);
        dwv[2] = ffma2(s_dw[2 * 9 + wb + 0], t0c2, dwv[2]);
        dwv[2] = ffma2(s_dw[2 * 9 + wb + 1], t1c2, dwv[2]);
        dwv[2] = ffma2(s_dw[2 * 9 + wb + 2], t2c2, dwv[2]);
        dwv[3] = ffma2(s_dw[3 * 9 + wb + 0], t0c3, dwv[3]);
        dwv[3] = ffma2(s_dw[3 * 9 + wb + 1], t1c3, dwv[3]);
        dwv[3] = ffma2(s_dw[3 * 9 + wb + 2], t2c3, dwv[3]);
        dwv[4] = ffma2(s_dw[4 * 9 + wb + 0], t0c4, dwv[4]);
        dwv[4] = ffma2(s_dw[4 * 9 + wb + 1], t1c4, dwv[4]);
        dwv[4] = ffma2(s_dw[4 * 9 + wb + 2], t2c4, dwv[4]);
    }

    __half2* outp = (__half2*)(g_f1 + ((size_t)b * 32) * (H1 * W1) + (size_t)oy * W1) + tx;
    #pragma unroll
    for (int o = 0; o < 32; o++) {
        u64 acc = s_pb[o];
        #pragma unroll
        for (int c = 0; c < 5; c++) acc = ffma2(s_pw[o * 5 + c], dwv[c], acc);
        float v0, v1; unpack2(acc, v0, v1);
        outp[(size_t)o * (H1 * W1 / 2)] = __floats2half2_rn(elu(v0), elu(v1));
    }
}

// ================= kernel 2: fused dwsep fp16 in/out, 2 pixels/thread, FFMA2, ILP-4 pw ==========
template <int CIN, int COUT, int HIN, int WIN, int HOUT, int WOUT>
__global__ void k_dwsep_p(const __half* __restrict__ in,
                          const float* __restrict__ dw,    // (CIN,1,3,3)
                          const float* __restrict__ pw_w,  // (COUT,CIN)
                          const float* __restrict__ pw_b,  // (COUT,)
                          __half* __restrict__ out)
{
    __shared__ u64 s_dw[CIN * 9];
    __shared__ u64 s_pw[COUT * CIN];
    __shared__ u64 s_pb[COUT];
    for (int i = threadIdx.x; i < CIN * 9;    i += blockDim.x) s_dw[i] = dup2(dw[i]);
    for (int i = threadIdx.x; i < COUT * CIN; i += blockDim.x) s_pw[i] = dup2(pw_w[i]);
    for (int i = threadIdx.x; i < COUT;       i += blockDim.x) s_pb[i] = dup2(pw_b[i]);
    __syncthreads();

    const int WP = WOUT / 2;
    int idx = blockIdx.x * blockDim.x + threadIdx.x;
    if (idx >= B * HOUT * WP) return;
    int tx = idx % WP;
    int t  = idx / WP;
    int oy = t % HOUT;
    int b  = t / HOUT;

    int col0 = 4 * tx - 2;
    bool left_ok = (tx > 0);

    u64 dwv[CIN];
    #pragma unroll
    for (int c = 0; c < CIN; c++) dwv[c] = pack2(0.f, 0.f);

    const __half* base = in + (size_t)b * CIN * (HIN * WIN);
    #pragma unroll
    for (int ky = 0; ky < 3; ky++) {
        int iy = oy * 2 - 1 + ky;
        if ((unsigned)iy >= HIN) continue;
        const __half* row = base + (size_t)iy * WIN + col0;
        int wb = ky * 3;
        #pragma unroll
        for (int c = 0; c < CIN; c++) {
            const __half2* rp = (const __half2*)(row + (size_t)c * (HIN * WIN));
            float2 A = left_ok ? __half22float2(rp[0]) : make_float2(0.f, 0.f);
            float2 Bv = __half22float2(rp[1]);
            float2 Cv = __half22float2(rp[2]);
            dwv[c] = ffma2(s_dw[c * 9 + wb + 0], pack2(A.y,  Bv.y), dwv[c]);
            dwv[c] = ffma2(s_dw[c * 9 + wb + 1], pack2(Bv.x, Cv.x), dwv[c]);
            dwv[c] = ffma2(s_dw[c * 9 + wb + 2], pack2(Bv.y, Cv.y), dwv[c]);
        }
    }

    // pointwise: 4 independent accumulator chains (o, o+Q, o+2Q, o+3Q)
    const int Q = COUT / 4;
    __half2* outp = (__half2*)(out + (size_t)b * COUT * (HOUT * WOUT) + (size_t)oy * WOUT) + tx;
    #pragma unroll 2
    for (int og = 0; og < Q; og++) {
        u64 a0 = s_pb[og];
        u64 a1 = s_pb[og + Q];
        u64 a2 = s_pb[og + 2 * Q];
        u64 a3 = s_pb[og + 3 * Q];
        #pragma unroll
        for (int c = 0; c < CIN; c++) {
            u64 d = dwv[c];
            a0 = ffma2(s_pw[(og)         * CIN + c], d, a0);
            a1 = ffma2(s_pw[(og + Q)     * CIN + c], d, a1);
            a2 = ffma2(s_pw[(og + 2 * Q) * CIN + c], d, a2);
            a3 = ffma2(s_pw[(og + 3 * Q) * CIN + c], d, a3);
        }
        float v0, v1;
        unpack2(a0, v0, v1);
        outp[(size_t)(og)         * (HOUT * WOUT / 2)] = __floats2half2_rn(elu(v0), elu(v1));
        unpack2(a1, v0, v1);
        outp[(size_t)(og + Q)     * (HOUT * WOUT / 2)] = __floats2half2_rn(elu(v0), elu(v1));
        unpack2(a2, v0, v1);
        outp[(size_t)(og + 2 * Q) * (HOUT * WOUT / 2)] = __floats2half2_rn(elu(v0), elu(v1));
        unpack2(a3, v0, v1);
        outp[(size_t)(og + 3 * Q) * (HOUT * WOUT / 2)] = __floats2half2_rn(elu(v0), elu(v1));
    }
}

// ================= kernel 3: dwsep fp16->fp32 + attn logit, oc-pair FFMA2, ILP-4 ==========
template <int CIN, int COUT, int HIN, int WIN, int HOUT, int WOUT>
__global__ void k_dwsep_logit(const __half* __restrict__ in,
                              const float* __restrict__ dw,
                              const float* __restrict__ pw_w,
                              const float* __restrict__ pw_b,
                              const float* __restrict__ attn_w,  // (COUT,)
                              const float* __restrict__ attn_b,  // (1,)
                              float* __restrict__ out,
                              float* __restrict__ logits)
{
    __shared__ float s_dw[CIN * 9];
    __shared__ u64 s_pw2[(COUT / 2) * CIN];   // (w[2o],w[2o+1]) pairs
    __shared__ u64 s_pb2[COUT / 2];
    __shared__ u64 s_aw2[COUT / 2];
    for (int i = threadIdx.x; i < CIN * 9; i += blockDim.x) s_dw[i] = dw[i];
    for (int i = threadIdx.x; i < (COUT / 2) * CIN; i += blockDim.x) {
        int o2 = i / CIN, c = i % CIN;
        s_pw2[i] = pack2(pw_w[(2 * o2) * CIN + c], pw_w[(2 * o2 + 1) * CIN + c]);
    }
    for (int i = threadIdx.x; i < COUT / 2; i += blockDim.x) {
        s_pb2[i] = pack2(pw_b[2 * i], pw_b[2 * i + 1]);
        s_aw2[i] = pack2(attn_w[2 * i], attn_w[2 * i + 1]);
    }
    __syncthreads();

    int idx = blockIdx.x * blockDim.x + threadIdx.x;
    if (idx >= B * HOUT * WOUT) return;
    int ox = idx % WOUT;
    int t  = idx / WOUT;
    int oy = t % HOUT;
    int b  = t / HOUT;

    float dwv[CIN];
    #pragma unroll
    for (int c = 0; c < CIN; c++) dwv[c] = 0.f;

    const __half* base = in + (size_t)b * CIN * (HIN * WIN);
    #pragma unroll
    for (int ky = 0; ky < 3; ky++) {
        int iy = oy * 2 - 1 + ky;
        if ((unsigned)iy >= HIN) continue;
        #pragma unroll
        for (int kx = 0; kx < 3; kx++) {
            int ix = ox * 2 - 1 + kx;
            if ((unsigned)ix >= WIN) continue;
            int w = ky * 3 + kx;
            const __half* p = base + (size_t)iy * WIN + ix;
            #pragma unroll
            for (int c = 0; c < CIN; c++)
                dwv[c] = fmaf(s_dw[c * 9 + w], __half2float(p[(size_t)c * (HIN * WIN)]), dwv[c]);
        }
    }

    // pw: 4 independent oc-pair chains
    const int Q = COUT / 8;   // oc-pair groups per chain (COUT/2 pairs / 4 chains)
    float* outp = out + (size_t)b * COUT * (HOUT * WOUT) + (size_t)oy * WOUT + ox;
    u64 logit2 = pack2(0.f, 0.f);
    #pragma unroll 2
    for (int jg = 0; jg < Q; jg++) {
        u64 a0 = s_pb2[jg];
        u64 a1 = s_pb2[jg + Q];
        u64 a2 = s_pb2[jg + 2 * Q];
        u64 a3 = s_pb2[jg + 3 * Q];
        #pragma unroll
        for (int c = 0; c < CIN; c++) {
            u64 d = dup2(dwv[c]);
            a0 = ffma2(s_pw2[(jg)         * CIN + c], d, a0);
            a1 = ffma2(s_pw2[(jg + Q)     * CIN + c], d, a1);
            a2 = ffma2(s_pw2[(jg + 2 * Q) * CIN + c], d, a2);
            a3 = ffma2(s_pw2[(jg + 3 * Q) * CIN + c], d, a3);
        }
        u64 accs[4] = {a0, a1, a2, a3};
        #pragma unroll
        for (int j = 0; j < 4; j++) {
            int o2 = jg + j * Q;
            float v0, v1; unpack2(accs[j], v0, v1);
            v0 = elu(v0); v1 = elu(v1);
            outp[(size_t)(2 * o2)     * (HOUT * WOUT)] = v0;
            outp[(size_t)(2 * o2 + 1) * (HOUT * WOUT)] = v1;
            logit2 = ffma2(s_aw2[o2], pack2(v0, v1), logit2);
        }
    }
    float l0, l1; unpack2(logit2, l0, l1);
    logits[b * (HOUT * WOUT) + oy * WOUT + ox] = l0 + l1 + attn_b[0];
}

// ================= kernel 4a: per-batch softmax -> normalized weights =================
#define SMX_T 512
__global__ void k4a_softmax()
{
    __shared__ float s_l[N3];
    __shared__ float s_red[SMX_T / 32];
    __shared__ float s_bcast;

    int b = blockIdx.x;
    int tid = threadIdx.x;
    int lane = tid & 31, warp = tid >> 5;
    const float* lg = g_logits + (size_t)b * N3;
    float* wt = g_wts + (size_t)b * N3;

    float lmax = -1e30f;
    for (int n = tid; n < N3; n += SMX_T) {
        float v = lg[n];
        s_l[n] = v;
        lmax = fmaxf(lmax, v);
    }
    #pragma unroll
    for (int o = 16; o > 0; o >>= 1) lmax = fmaxf(lmax, __shfl_xor_sync(0xffffffff, lmax, o));
    if (lane == 0) s_red[warp] = lmax;
    __syncthreads();
    if (warp == 0) {
        float v = (lane < SMX_T / 32) ? s_red[lane] : -1e30f;
        #pragma unroll
        for (int o = 16; o > 0; o >>= 1) v = fmaxf(v, __shfl_xor_sync(0xffffffff, v, o));
        if (lane == 0) s_bcast = v;
    }
    __syncthreads();
    float gmax = s_bcast;

    float lsum = 0.f;
    for (int n = tid; n < N3; n += SMX_T) {
        float e = expf(s_l[n] - gmax);
        s_l[n] = e;
        lsum += e;
    }
    #pragma unroll
    for (int o = 16; o > 0; o >>= 1) lsum += __shfl_xor_sync(0xffffffff, lsum, o);
    if (lane == 0) s_red[warp] = lsum;
    __syncthreads();
    if (warp == 0) {
        float v = (lane < SMX_T / 32) ? s_red[lane] : 0.f;
        #pragma unroll
        for (int o = 16; o > 0; o >>= 1) v += __shfl_xor_sync(0xffffffff, v, o);
        if (lane == 0) s_bcast = v;
    }
    __syncthreads();
    float inv_sum = 1.0f / s_bcast;

    for (int n = tid; n < N3; n += SMX_T) wt[n] = s_l[n] * inv_sum;
}

// ================= kernel 4b: pooled[b][c] = dot(f3[b,c,:], wts[b,:]) =================
#define POOL_T 256
__global__ void k4b_pool()
{
    int c = blockIdx.x;
    int b = blockIdx.y;
    int tid = threadIdx.x;
    int lane = tid & 31, warp = tid >> 5;
    __shared__ float s_red[POOL_T / 32];

    const float* fc = g_f3 + ((size_t)b * 64 + c) * N3;
    const float* wt = g_wts + (size_t)b * N3;

    float acc = 0.f;
    for (int n = tid; n < N3; n += POOL_T)
        acc = fmaf(wt[n], fc[n], acc);
    #pragma unroll
    for (int o = 16; o > 0; o >>= 1) acc += __shfl_xor_sync(0xffffffff, acc, o);
    if (lane == 0) s_red[warp] = acc;
    __syncthreads();
    if (warp == 0) {
        float v = (lane < POOL_T / 32) ? s_red[lane] : 0.f;
        #pragma unroll
        for (int o = 16; o > 0; o >>= 1) v += __shfl_xor_sync(0xffffffff, v, o);
        if (lane == 0) g_pooled[b * 64 + c] = v;
    }
}

// ================= kernel 5: MLP + GRU + fc (1 block / batch) =================
__global__ void k5_head(const float* __restrict__ mlp1_w, const float* __restrict__ mlp1_b,
                        const float* __restrict__ mlp2_w, const float* __restrict__ mlp2_b,
                        const float* __restrict__ w_ih,   const float* __restrict__ b_ih,
                        const float* __restrict__ b_hh,
                        const float* __restrict__ fc_w,   const float* __restrict__ fc_b,
                        float* __restrict__ out)
{
    __shared__ float s_pool[64];
    __shared__ float s_h1[32];
    __shared__ float s_om[3];
    __shared__ float s_gi[96];
    __shared__ float s_h[32];

    int b = blockIdx.x;
    int t = threadIdx.x;

    if (t < 64) s_pool[t] = g_pooled[b * 64 + t];
    __syncthreads();

    if (t < 32) {
        float acc = mlp1_b[t];
        #pragma unroll
        for (int c = 0; c < 64; c++) acc = fmaf(mlp1_w[t * 64 + c], s_pool[c], acc);
        s_h1[t] = acc > 0.f ? acc : (expf(acc) - 1.f);
    }
    __syncthreads();

    if (t < 3) {
        float acc = mlp2_b[t];
        #pragma unroll
        for (int c = 0; c < 32; c++) acc = fmaf(mlp2_w[t * 32 + c], s_h1[c], acc);
        s_om[t] = acc;
    }
    __syncthreads();

    if (t < 96) {
        float acc = b_ih[t];
        #pragma unroll
        for (int k = 0; k < 3; k++) acc = fmaf(w_ih[t * 3 + k], s_om[k], acc);
        s_gi[t] = acc;
    }
    __syncthreads();

    if (t < 32) {
        float r = 1.0f / (1.0f + expf(-(s_gi[t]      + b_hh[t])));
        float z = 1.0f / (1.0f + expf(-(s_gi[32 + t] + b_hh[32 + t])));
        float n = tanhf(s_gi[64 + t] + r * b_hh[64 + t]);
        s_h[t] = (1.0f - z) * n;
    }
    __syncthreads();

    if (t < 3) {
        float d = fc_b[t];
        #pragma unroll
        for (int j = 0; j < 32; j++) d = fmaf(fc_w[t * 32 + j], s_h[j], d);
        out[b * 3 + t] = s_om[t] + d;
    }
}

// ================= launch =================
extern "C" void kernel_launch(void* const* d_in, const int* in_sizes, int n_in,
                              void* d_out, int out_size)
{
    const float* flow   = (const float*)d_in[0];
    const float* dw1    = (const float*)d_in[1];
    const float* pw1_w  = (const float*)d_in[2];
    const float* pw1_b  = (const float*)d_in[3];
    const float* dw2    = (const float*)d_in[4];
    const float* pw2_w  = (const float*)d_in[5];
    const float* pw2_b  = (const float*)d_in[6];
    const float* dw3    = (const float*)d_in[7];
    const float* pw3_w  = (const float*)d_in[8];
    const float* pw3_b  = (const float*)d_in[9];
    const float* attn_w = (const float*)d_in[10];
    const float* attn_b = (const float*)d_in[11];
    const float* mlp1_w = (const float*)d_in[12];
    const float* mlp1_b = (const float*)d_in[13];
    const float* mlp2_w = (const float*)d_in[14];
    const float* mlp2_b = (const float*)d_in[15];
    const float* w_ih   = (const float*)d_in[16];
    // d_in[17] = w_hh (unused: h0 == 0)
    const float* b_ih   = (const float*)d_in[18];
    const float* b_hh   = (const float*)d_in[19];
    const float* fc_w   = (const float*)d_in[20];
    const float* fc_b   = (const float*)d_in[21];
    float* out = (float*)d_out;

    __half* f1; cudaGetSymbolAddress((void**)&f1, g_f1);
    __half* f2; cudaGetSymbolAddress((void**)&f2, g_f2);
    float*  f3; cudaGetSymbolAddress((void**)&f3, g_f3);
    float*  lg; cudaGetSymbolAddress((void**)&lg, g_logits);

    {
        int total = B * H1 * (W1 / 2);
        k1_dwsep1<<<(total + 255) / 256, 256>>>(flow, dw1, pw1_w, pw1_b);
    }
    {
        int total = B * H2 * (W2 / 2);
        k_dwsep_p<32, 64, H1, W1, H2, W2><<<(total + 127) / 128, 128>>>(f1, dw2, pw2_w, pw2_b, f2);
    }
    {
        int total = B * H3 * W3;
        k_dwsep_logit<64, 64, H2, W2, H3, W3><<<(total + 127) / 128, 128>>>(
            f2, dw3, pw3_w, pw3_b, attn_w, attn_b, f3, lg);
    }
    k4a_softmax<<<B, SMX_T>>>();
    {
        dim3 grid(64, B);
        k4b_pool<<<grid, POOL_T>>>();
    }
    k5_head<<<B, 96>>>(mlp1_w, mlp1_b, mlp2_w, mlp2_b,
                       w_ih, b_ih, b_hh, fc_w, fc_b, out);
}